// round 2
// baseline (speedup 1.0000x reference)
#include <cuda_runtime.h>
#include <math.h>
#include <float.h>

#define EPSV 1e-6f

static constexpr int Bq   = 1024;     // queries
static constexpr int Mk   = 100000;   // keys
static constexpr int Dd   = 256;      // dim
static constexpr int TOPK = 8;
static constexpr int VROW = 16 * 64;  // 1024 floats per value row

// Scratch (device-global arrays: the sanctioned no-cudaMalloc workaround)
__device__ float g_sim[(size_t)Bq * Mk];     // ~390 MB
__device__ float g_invq[Bq];
__device__ float g_invk[Mk];
__device__ int   g_topidx[Bq * TOPK];

// ---------------------------------------------------------------------------
// Kernel 1: inverse L2 norms (one warp per row), matching max(norm, eps)
// ---------------------------------------------------------------------------
__global__ void norms_kernel(const float* __restrict__ q,
                             const float* __restrict__ k) {
    int w    = (blockIdx.x * blockDim.x + threadIdx.x) >> 5;
    int lane = threadIdx.x & 31;
    if (w >= Bq + Mk) return;
    const float* row = (w < Bq) ? (q + (size_t)w * Dd)
                                : (k + (size_t)(w - Bq) * Dd);
    float s = 0.f;
#pragma unroll
    for (int i = 0; i < Dd / 32; i++) {
        float v = row[lane + i * 32];
        s = fmaf(v, v, s);
    }
#pragma unroll
    for (int o = 16; o; o >>= 1) s += __shfl_xor_sync(0xffffffffu, s, o);
    if (lane == 0) {
        float inv = 1.0f / fmaxf(sqrtf(s), EPSV);
        if (w < Bq) g_invq[w] = inv; else g_invk[w - Bq] = inv;
    }
}

// ---------------------------------------------------------------------------
// Kernel 2: sim = Qn * Kn^T   (fp32, packed f32x2 FMA)
// CTA tile: 128 (b) x 128 (m), K-step 16, 256 threads, 8x8 per thread.
// ---------------------------------------------------------------------------
#define QP 132  // smem row pitch in floats (132*4 % 16 == 0, breaks bank stride)

__global__ void __launch_bounds__(256)
gemm_kernel(const float* __restrict__ Q, const float* __restrict__ K) {
    __shared__ float Qs[16 * QP];
    __shared__ float Ks[16 * QP];
    __shared__ float s_invk[128];
    __shared__ float s_invq[128];

    const int tid   = threadIdx.x;
    const int tx    = tid & 15;   // m-subtile (8 consecutive m's)
    const int ty    = tid >> 4;   // b-subtile (8 consecutive b's)
    const int mBase = blockIdx.x * 128;
    const int bBase = blockIdx.y * 128;

    unsigned long long acc[8][4];  // packed f32x2: [b-row][m-pair]
#pragma unroll
    for (int i = 0; i < 8; i++)
#pragma unroll
        for (int j = 0; j < 4; j++) acc[i][j] = 0ull;

    for (int kt = 0; kt < Dd; kt += 16) {
        // Load 128x16 tiles of Q and K (transposed into smem as [k][row])
#pragma unroll
        for (int t = 0; t < 2; t++) {
            int f  = tid + t * 256;        // float4 index 0..511
            int r  = f >> 2;               // row in tile (0..127)
            int c4 = f & 3;                // float4 within the 16 k's
            float4 v = *(const float4*)(Q + (size_t)(bBase + r) * Dd + kt + c4 * 4);
            Qs[(c4 * 4 + 0) * QP + r] = v.x;
            Qs[(c4 * 4 + 1) * QP + r] = v.y;
            Qs[(c4 * 4 + 2) * QP + r] = v.z;
            Qs[(c4 * 4 + 3) * QP + r] = v.w;
            int mr = mBase + r;
            float4 u = make_float4(0.f, 0.f, 0.f, 0.f);
            if (mr < Mk)
                u = *(const float4*)(K + (size_t)mr * Dd + kt + c4 * 4);
            Ks[(c4 * 4 + 0) * QP + r] = u.x;
            Ks[(c4 * 4 + 1) * QP + r] = u.y;
            Ks[(c4 * 4 + 2) * QP + r] = u.z;
            Ks[(c4 * 4 + 3) * QP + r] = u.w;
        }
        __syncthreads();

#pragma unroll
        for (int k = 0; k < 16; k++) {
            float a[8];
            const float* qrow = &Qs[k * QP + ty * 8];
            *(float4*)&a[0] = *(const float4*)(qrow);
            *(float4*)&a[4] = *(const float4*)(qrow + 4);
            const unsigned long long* brow =
                (const unsigned long long*)&Ks[k * QP + tx * 8];
            unsigned long long b0 = brow[0], b1 = brow[1],
                               b2 = brow[2], b3 = brow[3];
#pragma unroll
            for (int i = 0; i < 8; i++) {
                unsigned au = __float_as_uint(a[i]);
                unsigned long long a2;
                asm("mov.b64 %0, {%1, %1};" : "=l"(a2) : "r"(au));
                asm("fma.rn.f32x2 %0, %1, %2, %0;" : "+l"(acc[i][0]) : "l"(a2), "l"(b0));
                asm("fma.rn.f32x2 %0, %1, %2, %0;" : "+l"(acc[i][1]) : "l"(a2), "l"(b1));
                asm("fma.rn.f32x2 %0, %1, %2, %0;" : "+l"(acc[i][2]) : "l"(a2), "l"(b2));
                asm("fma.rn.f32x2 %0, %1, %2, %0;" : "+l"(acc[i][3]) : "l"(a2), "l"(b3));
            }
        }
        __syncthreads();
    }

    // Stage inverse norms for this tile
    if (tid < 128) {
        int mm = mBase + tid;
        s_invk[tid] = (mm < Mk) ? g_invk[mm] : 0.f;
        s_invq[tid] = g_invq[bBase + tid];
    }
    __syncthreads();

    // Epilogue: scale + coalesced float4 stores (M % 8 == 0, so one guard)
    const int mrow = mBase + tx * 8;
    if (mrow < Mk) {
#pragma unroll
        for (int i = 0; i < 8; i++) {
            int   bi = bBase + ty * 8 + i;
            float sq = s_invq[ty * 8 + i];
            float c[8];
#pragma unroll
            for (int j = 0; j < 4; j++) {
                c[2 * j]     = __uint_as_float((unsigned)(acc[i][j] & 0xffffffffull));
                c[2 * j + 1] = __uint_as_float((unsigned)(acc[i][j] >> 32));
            }
            float4 o0, o1;
            o0.x = c[0] * sq * s_invk[tx * 8 + 0];
            o0.y = c[1] * sq * s_invk[tx * 8 + 1];
            o0.z = c[2] * sq * s_invk[tx * 8 + 2];
            o0.w = c[3] * sq * s_invk[tx * 8 + 3];
            o1.x = c[4] * sq * s_invk[tx * 8 + 4];
            o1.y = c[5] * sq * s_invk[tx * 8 + 5];
            o1.z = c[6] * sq * s_invk[tx * 8 + 6];
            o1.w = c[7] * sq * s_invk[tx * 8 + 7];
            float* dst = g_sim + (size_t)bi * Mk + mrow;
            *(float4*)dst       = o0;
            *(float4*)(dst + 4) = o1;
        }
    }
}

// ---------------------------------------------------------------------------
// Kernel 3: exact top-8 per query, jax tie-break (value desc, index asc)
// ---------------------------------------------------------------------------
__device__ __forceinline__ bool better(float v1, int i1, float v2, int i2) {
    return (v1 > v2) || (v1 == v2 && i1 < i2);
}

__global__ void __launch_bounds__(256) topk_kernel() {
    __shared__ float sv[2048];
    __shared__ int   si[2048];
    __shared__ float rv[256];
    __shared__ int   ridx[256];
    __shared__ int   rpos[256];

    const int b   = blockIdx.x;
    const int tid = threadIdx.x;
    const float* sim = g_sim + (size_t)b * Mk;

    float lv[8];
    int   li[8];
#pragma unroll
    for (int j = 0; j < 8; j++) { lv[j] = -FLT_MAX; li[j] = 0x7fffffff; }

    for (int m = tid; m < Mk; m += 256) {
        float v = __ldg(sim + m);
        if (better(v, m, lv[7], li[7])) {          // cheap reject fast path
            // branchless sorted insert (static indices -> stays in registers)
#pragma unroll
            for (int j = 7; j >= 0; j--) {
                bool b_cur  = better(v, m, lv[j], li[j]);
                bool b_prev = (j > 0) ? better(v, m, lv[j - 1], li[j - 1]) : false;
                float nv = b_prev ? lv[j - 1] : (b_cur ? v : lv[j]);
                int   ni = b_prev ? li[j - 1] : (b_cur ? m : li[j]);
                lv[j] = nv; li[j] = ni;
            }
        }
    }

#pragma unroll
    for (int j = 0; j < 8; j++) { sv[tid * 8 + j] = lv[j]; si[tid * 8 + j] = li[j]; }
    __syncthreads();

    for (int sel = 0; sel < TOPK; sel++) {
        float bv = -FLT_MAX; int bidx = 0x7fffffff; int bpos = 0;
#pragma unroll
        for (int j = 0; j < 8; j++) {
            int p = tid * 8 + j;
            if (better(sv[p], si[p], bv, bidx)) { bv = sv[p]; bidx = si[p]; bpos = p; }
        }
        rv[tid] = bv; ridx[tid] = bidx; rpos[tid] = bpos;
        __syncthreads();
        for (int s = 128; s > 0; s >>= 1) {
            if (tid < s) {
                if (better(rv[tid + s], ridx[tid + s], rv[tid], ridx[tid])) {
                    rv[tid] = rv[tid + s]; ridx[tid] = ridx[tid + s]; rpos[tid] = rpos[tid + s];
                }
            }
            __syncthreads();
        }
        if (tid == 0) {
            g_topidx[b * TOPK + sel] = ridx[0];
            sv[rpos[0]] = -FLT_MAX;
            si[rpos[0]] = 0x7fffffff;
        }
        __syncthreads();
    }
}

// ---------------------------------------------------------------------------
// Kernel 4: gather values[idx] -> out  (one CTA per output row, float4 copy)
// ---------------------------------------------------------------------------
__global__ void __launch_bounds__(256)
gather_kernel(const float* __restrict__ values, float* __restrict__ out) {
    int r   = blockIdx.x;           // b*8 + j
    int idx = g_topidx[r];
    const float4* src = (const float4*)(values + (size_t)idx * VROW);
    float4*       dst = (float4*)(out + (size_t)r * VROW);
    dst[threadIdx.x] = __ldg(src + threadIdx.x);
}

// ---------------------------------------------------------------------------
extern "C" void kernel_launch(void* const* d_in, const int* in_sizes, int n_in,
                              void* d_out, int out_size) {
    const float* q = (const float*)d_in[0];
    const float* k = (const float*)d_in[1];
    const float* v = (const float*)d_in[2];
    // d_in[3] = top_num (device scalar); fixed shape problem -> TOPK = 8.

    int totalWarps = Bq + Mk;
    norms_kernel<<<(totalWarps * 32 + 255) / 256, 256>>>(q, k);
    gemm_kernel<<<dim3((Mk + 127) / 128, Bq / 128), 256>>>(q, k);
    topk_kernel<<<Bq, 256>>>();
    gather_kernel<<<Bq * TOPK, 256>>>(v, (float*)d_out);
}

// round 6
// speedup vs baseline: 3.0550x; 3.0550x over previous
#include <cuda_runtime.h>
#include <cuda_bf16.h>
#include <stdint.h>
#include <cstdint>
#include <math.h>
#include <float.h>

static constexpr int Bq   = 1024;
static constexpr int Mk   = 100000;
static constexpr int Dd   = 256;
static constexpr int TOPK = 8;
static constexpr int VROW = 1024;
static constexpr int CANDMAX = 256;

static constexpr int BM = 128;   // queries per CTA
static constexpr int BN = 128;   // keys per CTA
static constexpr int BK = 64;    // k-chunk
static constexpr int MT_X = (Mk + BN - 1) / BN;   // 782 key tiles

// ---------------- device scratch ----------------
__device__ unsigned short g_qnh[(size_t)Bq * Dd];
__device__ unsigned short g_knh[(size_t)Mk * Dd];
__device__ unsigned short g_simh[(size_t)Bq * Mk];
__device__ float g_invq[Bq];
__device__ float g_invk[Mk];
__device__ int   g_cand[Bq * CANDMAX];
__device__ int   g_cnt[Bq];
__device__ int   g_topidx[Bq * TOPK];

__device__ __forceinline__ unsigned smem_u32(const void* p) {
    unsigned a;
    asm("{ .reg .u64 t; cvta.to.shared.u64 t, %1; cvt.u32.u64 %0, t; }"
        : "=r"(a) : "l"(p));
    return a;
}
#define CP_ASYNC16(saddr, gptr, sz) \
    asm volatile("cp.async.cg.shared.global [%0], [%1], 16, %2;" \
                 :: "r"(saddr), "l"(gptr), "r"(sz))
#define CP_COMMIT()  asm volatile("cp.async.commit_group;" ::: "memory")
#define CP_WAIT(n)   asm volatile("cp.async.wait_group %0;" :: "n"(n) : "memory")
#define LDSM_X4(r0, r1, r2, r3, a) \
    asm volatile("ldmatrix.sync.aligned.m8n8.x4.shared.b16 {%0,%1,%2,%3}, [%4];" \
                 : "=r"(r0), "=r"(r1), "=r"(r2), "=r"(r3) : "r"(a))
#define MMA16816(c0, c1, c2, c3, a0, a1, a2, a3, b0, b1) \
    asm volatile("mma.sync.aligned.m16n8k16.row.col.f32.bf16.bf16.f32 " \
                 "{%0,%1,%2,%3}, {%4,%5,%6,%7}, {%8,%9}, {%0,%1,%2,%3};" \
                 : "+f"(c0), "+f"(c1), "+f"(c2), "+f"(c3) \
                 : "r"(a0), "r"(a1), "r"(a2), "r"(a3), "r"(b0), "r"(b1))

// ---------------------------------------------------------------------------
// Kernel 1: fused norm + normalize + bf16 cast (one warp per row)
// ---------------------------------------------------------------------------
__global__ void normalize_kernel(const float* __restrict__ q,
                                 const float* __restrict__ k) {
    int w    = (blockIdx.x * blockDim.x + threadIdx.x) >> 5;
    int lane = threadIdx.x & 31;
    if (w >= Bq + Mk) return;
    const float* row;
    unsigned short* outp;
    if (w < Bq) { row = q + (size_t)w * Dd; outp = g_qnh + (size_t)w * Dd; }
    else        { row = k + (size_t)(w - Bq) * Dd; outp = g_knh + (size_t)(w - Bq) * Dd; }
    float4 v0 = ((const float4*)row)[lane];
    float4 v1 = ((const float4*)row)[lane + 32];
    float s = v0.x * v0.x + v0.y * v0.y + v0.z * v0.z + v0.w * v0.w
            + v1.x * v1.x + v1.y * v1.y + v1.z * v1.z + v1.w * v1.w;
#pragma unroll
    for (int o = 16; o; o >>= 1) s += __shfl_xor_sync(0xffffffffu, s, o);
    float inv = 1.0f / fmaxf(sqrtf(s), 1e-6f);
    if (lane == 0) { if (w < Bq) g_invq[w] = inv; else g_invk[w - Bq] = inv; }
    __nv_bfloat162 p0 = __floats2bfloat162_rn(v0.x * inv, v0.y * inv);
    __nv_bfloat162 p1 = __floats2bfloat162_rn(v0.z * inv, v0.w * inv);
    __nv_bfloat162 p2 = __floats2bfloat162_rn(v1.x * inv, v1.y * inv);
    __nv_bfloat162 p3 = __floats2bfloat162_rn(v1.z * inv, v1.w * inv);
    uint2 o0 = make_uint2(*(unsigned*)&p0, *(unsigned*)&p1);
    uint2 o1 = make_uint2(*(unsigned*)&p2, *(unsigned*)&p3);
    ((uint2*)outp)[lane]      = o0;
    ((uint2*)outp)[lane + 32] = o1;
}

// ---------------------------------------------------------------------------
// Kernel 2: bf16 mma.sync GEMM  sim = Qn * Kn^T
// CTA: 128q x 128k, BK=64, cp.async double buffer, 8 warps (2x4), warp 64x32
// ---------------------------------------------------------------------------
static constexpr int STAGE_BYTES = BM * BK * 2 + BN * BK * 2;  // 32768
static constexpr int SMEM_GEMM   = 2 * STAGE_BYTES;            // 65536

__global__ void __launch_bounds__(256)
gemm_kernel() {
    extern __shared__ char dsm[];
    const unsigned sbase = smem_u32(dsm);
    const int tid = threadIdx.x;
    const int wid = tid >> 5, lane = tid & 31;
    const int warp_m = wid >> 2;        // 0..1 : 64 q-rows
    const int warp_n = wid & 3;         // 0..3 : 32 k-cols
    const int bBase = blockIdx.x * BM;  // query tile (fast dim: 8)
    const int mBase = blockIdx.y * BN;  // key tile (782)

    // per-thread load slots: 4 chunks Q + 4 chunks K per stage
    // chunk f in [0,1024): row = f>>3, c = f&7 (16B chunks of a 128B row)
    auto load_stage = [&](int stage, int kt) {
        unsigned qs = sbase + stage * STAGE_BYTES;
        unsigned ks = qs + BM * BK * 2;
#pragma unroll
        for (int i = 0; i < 4; i++) {
            int f = tid + i * 256;
            int row = f >> 3, c = f & 7;
            unsigned sw = row * 128 + ((c ^ (row & 7)) << 4);
            const unsigned short* gq =
                g_qnh + (size_t)(bBase + row) * Dd + kt + c * 8;
            CP_ASYNC16(qs + sw, gq, 16);
            int m = mBase + row;
            int valid = (m < Mk) ? 16 : 0;
            const unsigned short* gk =
                g_knh + (size_t)(valid ? m : 0) * Dd + kt + c * 8;
            CP_ASYNC16(ks + sw, gk, valid);
        }
        CP_COMMIT();
    };

    float acc[4][4][4];
#pragma unroll
    for (int mt = 0; mt < 4; mt++)
#pragma unroll
        for (int nt = 0; nt < 4; nt++)
#pragma unroll
            for (int e = 0; e < 4; e++) acc[mt][nt][e] = 0.f;

    load_stage(0, 0);

    for (int it = 0; it < 4; it++) {
        if (it < 3) load_stage((it + 1) & 1, (it + 1) * BK);
        if (it < 3) { CP_WAIT(1); } else { CP_WAIT(0); }
        __syncthreads();

        unsigned qs = sbase + (it & 1) * STAGE_BYTES;
        unsigned ks = qs + BM * BK * 2;

#pragma unroll
        for (int kk = 0; kk < 4; kk++) {           // 4 x k16 within BK=64
            // A frags: 4 m-tiles of 16 rows
            unsigned a[4][4];
#pragma unroll
            for (int mt = 0; mt < 4; mt++) {
                int row = warp_m * 64 + mt * 16 + (lane & 15);
                int c   = kk * 2 + (lane >> 4);
                unsigned addr = qs + row * 128 + ((c ^ (row & 7)) << 4);
                LDSM_X4(a[mt][0], a[mt][1], a[mt][2], a[mt][3], addr);
            }
            // B frags: 2 x (n=16) ldmatrix.x4 -> 4 n-tiles
            unsigned b[4][2];
#pragma unroll
            for (int ntp = 0; ntp < 2; ntp++) {
                int row = warp_n * 32 + ntp * 16 + (lane & 15);
                int c   = kk * 2 + (lane >> 4);
                unsigned addr = ks + row * 128 + ((c ^ (row & 7)) << 4);
                unsigned r0, r1, r2, r3;
                LDSM_X4(r0, r1, r2, r3, addr);
                b[2 * ntp][0]     = r0; b[2 * ntp][1]     = r2;
                b[2 * ntp + 1][0] = r1; b[2 * ntp + 1][1] = r3;
            }
#pragma unroll
            for (int mt = 0; mt < 4; mt++)
#pragma unroll
                for (int nt = 0; nt < 4; nt++)
                    MMA16816(acc[mt][nt][0], acc[mt][nt][1],
                             acc[mt][nt][2], acc[mt][nt][3],
                             a[mt][0], a[mt][1], a[mt][2], a[mt][3],
                             b[nt][0], b[nt][1]);
        }
        __syncthreads();
    }

    // epilogue: bf16 sims
    const int r0 = bBase + warp_m * 64 + (lane >> 2);
    const int c0 = mBase + warp_n * 32 + (lane & 3) * 2;
#pragma unroll
    for (int mt = 0; mt < 4; mt++) {
#pragma unroll
        for (int nt = 0; nt < 4; nt++) {
            int col = c0 + nt * 8;
            if (col < Mk) {
                int rowa = r0 + mt * 16;
                __nv_bfloat162 pa = __floats2bfloat162_rn(acc[mt][nt][0], acc[mt][nt][1]);
                __nv_bfloat162 pb = __floats2bfloat162_rn(acc[mt][nt][2], acc[mt][nt][3]);
                *(unsigned*)(g_simh + (size_t)rowa * Mk + col)       = *(unsigned*)&pa;
                *(unsigned*)(g_simh + (size_t)(rowa + 8) * Mk + col) = *(unsigned*)&pb;
            }
        }
    }
}

// ---------------------------------------------------------------------------
// Kernel 3: candidate selection from bf16 sims
// ---------------------------------------------------------------------------
__device__ __forceinline__ bool better(float v1, int i1, float v2, int i2) {
    return (v1 > v2) || (v1 == v2 && i1 < i2);
}

__global__ void __launch_bounds__(256) cand_kernel() {
    __shared__ float sv[2048];
    __shared__ int   si[2048];
    __shared__ float rv[256];
    __shared__ int   ri[256];
    __shared__ int   rp[256];
    __shared__ int   s_cnt;
    __shared__ float s_tau;
    __shared__ int   s_list[CANDMAX];

    const int b = blockIdx.x, tid = threadIdx.x;
    if (tid == 0) s_cnt = 0;
    const uint4* sim = (const uint4*)(g_simh + (size_t)b * Mk);

    float lv[8]; int li[8];
#pragma unroll
    for (int j = 0; j < 8; j++) { lv[j] = -FLT_MAX; li[j] = 0x7fffffff; }

    for (int c = tid; c < Mk / 8; c += 256) {
        uint4 u = __ldg(sim + c);
        int m0 = c * 8;
        unsigned ws[4] = {u.x, u.y, u.z, u.w};
#pragma unroll
        for (int h = 0; h < 4; h++) {
            float v0 = __uint_as_float(ws[h] << 16);
            float v1 = __uint_as_float(ws[h] & 0xffff0000u);
            int   m  = m0 + h * 2;
#pragma unroll
            for (int e = 0; e < 2; e++) {
                float v = e ? v1 : v0; int mm = m + e;
                if (better(v, mm, lv[7], li[7])) {
#pragma unroll
                    for (int j = 7; j >= 0; j--) {
                        bool bc = better(v, mm, lv[j], li[j]);
                        bool bp = (j > 0) ? better(v, mm, lv[j - 1], li[j - 1]) : false;
                        float nv = bp ? lv[j - 1] : (bc ? v : lv[j]);
                        int   ni = bp ? li[j - 1] : (bc ? mm : li[j]);
                        lv[j] = nv; li[j] = ni;
                    }
                }
            }
        }
    }
#pragma unroll
    for (int j = 0; j < 8; j++) { sv[tid * 8 + j] = lv[j]; si[tid * 8 + j] = li[j]; }
    __syncthreads();

    for (int sel = 0; sel < TOPK; sel++) {
        float bv = -FLT_MAX; int bi = 0x7fffffff; int bp = 0;
#pragma unroll
        for (int j = 0; j < 8; j++) {
            int p = tid * 8 + j;
            if (better(sv[p], si[p], bv, bi)) { bv = sv[p]; bi = si[p]; bp = p; }
        }
        rv[tid] = bv; ri[tid] = bi; rp[tid] = bp;
        __syncthreads();
        for (int s = 128; s > 0; s >>= 1) {
            if (tid < s && better(rv[tid + s], ri[tid + s], rv[tid], ri[tid])) {
                rv[tid] = rv[tid + s]; ri[tid] = ri[tid + s]; rp[tid] = rp[tid + s];
            }
            __syncthreads();
        }
        if (tid == 0) {
            if (sel == TOPK - 1) s_tau = rv[0] - 0.01f;
            sv[rp[0]] = -FLT_MAX; si[rp[0]] = 0x7fffffff;
        }
        __syncthreads();
    }

#pragma unroll
    for (int j = 0; j < 8; j++) {
        if (lv[j] >= s_tau && li[j] < Mk) {
            int p = atomicAdd(&s_cnt, 1);
            if (p < CANDMAX) s_list[p] = li[j];
        }
    }
    __syncthreads();
    int n = min(s_cnt, CANDMAX);
    if (tid == 0) g_cnt[b] = n;
    if (tid < n) g_cand[b * CANDMAX + tid] = s_list[tid];
}

// ---------------------------------------------------------------------------
// Kernel 4: exact fp32 rescore of candidates + exact top-8
// ---------------------------------------------------------------------------
__global__ void __launch_bounds__(256)
rescore_kernel(const float* __restrict__ q, const float* __restrict__ k) {
    __shared__ float qs[256];
    __shared__ float cval[CANDMAX];
    __shared__ int   cidx[CANDMAX];
    __shared__ float rv[256];
    __shared__ int   ri[256];
    __shared__ int   rp[256];

    const int b = blockIdx.x, tid = threadIdx.x;
    const int n = g_cnt[b];
    qs[tid] = q[(size_t)b * Dd + tid];
    cval[tid] = -FLT_MAX;
    cidx[tid] = 0x7fffffff;
    if (tid < n) cidx[tid] = g_cand[b * CANDMAX + tid];
    __syncthreads();

    const int w = tid >> 5, lane = tid & 31;
    const float invq = g_invq[b];
    for (int c = w; c < n; c += 8) {
        int key = cidx[c];
        const float4* kr = (const float4*)(k + (size_t)key * Dd);
        float4 a0 = __ldg(kr + lane * 2);
        float4 a1 = __ldg(kr + lane * 2 + 1);
        const float* qp = qs + lane * 8;
        float s = a0.x * qp[0] + a0.y * qp[1] + a0.z * qp[2] + a0.w * qp[3]
                + a1.x * qp[4] + a1.y * qp[5] + a1.z * qp[6] + a1.w * qp[7];
#pragma unroll
        for (int o = 16; o; o >>= 1) s += __shfl_xor_sync(0xffffffffu, s, o);
        if (lane == 0) cval[c] = s * invq * g_invk[key];
    }
    __syncthreads();

    for (int sel = 0; sel < TOPK; sel++) {
        rv[tid] = cval[tid]; ri[tid] = cidx[tid]; rp[tid] = tid;
        __syncthreads();
        for (int s = 128; s > 0; s >>= 1) {
            if (tid < s && better(rv[tid + s], ri[tid + s], rv[tid], ri[tid])) {
                rv[tid] = rv[tid + s]; ri[tid] = ri[tid + s]; rp[tid] = rp[tid + s];
            }
            __syncthreads();
        }
        if (tid == 0) {
            g_topidx[b * TOPK + sel] = ri[0];
            cval[rp[0]] = -FLT_MAX; cidx[rp[0]] = 0x7fffffff;
        }
        __syncthreads();
    }
}

// ---------------------------------------------------------------------------
// Kernel 5: gather values[idx] -> out
// ---------------------------------------------------------------------------
__global__ void __launch_bounds__(256)
gather_kernel(const float* __restrict__ values, float* __restrict__ out) {
    int r   = blockIdx.x;
    int idx = g_topidx[r];
    const float4* src = (const float4*)(values + (size_t)idx * VROW);
    float4*       dst = (float4*)(out + (size_t)r * VROW);
    dst[threadIdx.x] = __ldg(src + threadIdx.x);
}

// ---------------------------------------------------------------------------
extern "C" void kernel_launch(void* const* d_in, const int* in_sizes, int n_in,
                              void* d_out, int out_size) {
    const float* q = (const float*)d_in[0];
    const float* k = (const float*)d_in[1];
    const float* v = (const float*)d_in[2];

    int totalWarps = Bq + Mk;
    normalize_kernel<<<(totalWarps * 32 + 255) / 256, 256>>>(q, k);

    static int smem_set = 0;
    if (!smem_set) {
        cudaFuncSetAttribute(gemm_kernel,
                             cudaFuncAttributeMaxDynamicSharedMemorySize, SMEM_GEMM);
        smem_set = 1;
    }
    gemm_kernel<<<dim3(Bq / BM, MT_X), 256, SMEM_GEMM>>>();

    cand_kernel<<<Bq, 256>>>();
    rescore_kernel<<<Bq, 256>>>(q, k);
    gather_kernel<<<Bq * TOPK, 256>>>(v, (float*)d_out);
}